// round 14
// baseline (speedup 1.0000x reference)
#include <cuda_runtime.h>
#include <cuda_fp16.h>
#include <math.h>
#include <cstdint>

#define NB   128
#define CIN  3
#define DIN  18
#define HIN  34
#define WIN  34
#define HW   (HIN * WIN)
#define COUT 16
#define DOUT 16
#define HOUT 32
#define WOUT 32

#define NKS     7            // 112 k = 56 pairs = 7 k-steps of 16
#define RS      40           // slab row stride (u32),  == 8  mod 32
#define PS      1368         // slab plane stride (u32),== 24 mod 32
#define SLAB32  (9 * PS + 48)     // 12360 u32 slots

// dynamic smem: [ slab fp16x2 u32[SLAB32] | Bpack uint4[7*32] ]
#define DSMEM_BYTES (SLAB32 * 4 + NKS * 32 * 16)

// Scratch (device globals: allocation-free per harness rules)
// y fp16, channel-pair-interleaved channel-last:
//   px block (32B) = [c0c1 | c8c9 | c2c3 | c10c11 | c4c5 | c12c13 | c6c7 | c14c15]
__device__ __half2 g_yh[(size_t)NB * DOUT * 1024 * 8];          // 67 MB
__device__ float   g_part[NB * COUT * DOUT * 2];

__device__ __forceinline__ void mma_f16(float* c,
                                        uint32_t a0, uint32_t a1, uint32_t a2, uint32_t a3,
                                        uint32_t b0, uint32_t b1) {
    asm volatile(
        "mma.sync.aligned.m16n8k16.row.col.f32.f16.f16.f32 "
        "{%0,%1,%2,%3}, {%4,%5,%6,%7}, {%8,%9}, {%0,%1,%2,%3};"
        : "+f"(c[0]), "+f"(c[1]), "+f"(c[2]), "+f"(c[3])
        : "r"(a0), "r"(a1), "r"(a2), "r"(a3), "r"(b0), "r"(b1));
}

// weight for phase-major k': j=k>>1 pair index, i=k&1.
__device__ __forceinline__ float wval2(const float* __restrict__ cw, int c, int k) {
    const int j = k >> 1, i = k & 1;
    if (j < 27)              return cw[c * 81 + j * 3 + i];
    if (j >= 28 && j < 55 && i == 0) return cw[c * 81 + (j - 28) * 3 + 2];
    return 0.0f;
}

__global__ void dummy_kernel() {}

// ---------------------------------------------------------------------------
// Kernel 1: conv3d + bias + channel-mult, fp16 mma implicit GEMM.
// Fully unrolled tile loop: all LDS/STG use compile-time immediate offsets.
// Grid (DOUT, NB), 256 threads, 4 CTAs/SM.
// ---------------------------------------------------------------------------
__global__ void __launch_bounds__(256, 4) conv_kernel(
    const float* __restrict__ x,
    const float* __restrict__ cw,
    const float* __restrict__ cb,
    const float* __restrict__ mult)
{
    extern __shared__ uint32_t slab[];
    uint4* Bpack = (uint4*)(slab + SLAB32);

    __shared__ float sbm[2 * COUT];
    __shared__ float sred[8][COUT][2];

    const int tid = threadIdx.x;
    const int wid = tid >> 5;
    const int lid = tid & 31;
    const int d   = blockIdx.x;
    const int b   = blockIdx.y;

    // ---- build fp16x2 pair slab: slot p = (x[p], x[p+1]) ----
    const float* xb = x + (size_t)b * (CIN * DIN * HW);
    for (int i = tid; i < 9 * 1156; i += 256) {
        const int plane = i / 1156;              // ci*3 + kd
        const int pos   = i - plane * 1156;
        const int h     = pos / 34;
        const int w     = pos - h * 34;
        const int ci    = plane / 3;
        const int kd    = plane - ci * 3;
        const float* src = xb + ci * (DIN * HW) + (d + kd) * HW + pos;
        const float f0 = __ldg(src);
        const float f1 = (w < 33) ? __ldg(src + 1) : 0.0f;
        __half2 h2 = __floats2half2_rn(f0, f1);
        slab[plane * PS + h * RS + w] = *reinterpret_cast<uint32_t*>(&h2);
    }
    // tiny zero-fill: plane-8 row 34 (read by the j=27/55 pad quads at h=31)
    if (tid < 48) slab[8 * PS + 34 * RS + tid] = 0;

    // ---- build packed B-frag table (phase-major map): Bpack[ks*32 + lane] ----
    for (int i = tid; i < NKS * 32; i += 256) {
        const int ks  = i >> 5;
        const int l   = i & 31;
        const int tt4 = l & 3;
        const int gg  = l >> 2;
        const int k0  = ks * 16 + tt4 * 2;
        __half2 p0 = __floats2half2_rn(wval2(cw, gg, k0),     wval2(cw, gg, k0 + 1));
        __half2 p1 = __floats2half2_rn(wval2(cw, gg, k0 + 8), wval2(cw, gg, k0 + 9));
        __half2 p2 = __floats2half2_rn(wval2(cw, gg + 8, k0),     wval2(cw, gg + 8, k0 + 1));
        __half2 p3 = __floats2half2_rn(wval2(cw, gg + 8, k0 + 8), wval2(cw, gg + 8, k0 + 9));
        uint4 v;
        v.x = *reinterpret_cast<uint32_t*>(&p0);
        v.y = *reinterpret_cast<uint32_t*>(&p1);
        v.z = *reinterpret_cast<uint32_t*>(&p2);
        v.w = *reinterpret_cast<uint32_t*>(&p3);
        Bpack[i] = v;
    }
    if (tid < COUT) { sbm[tid] = mult[tid]; sbm[COUT + tid] = cb[tid] * mult[tid]; }
    __syncthreads();

    // ---- per-lane A slots with thread-constant part folded in ----
    const int t4 = lid & 3;
    const int g  = lid >> 2;
    const int h_lo = wid >> 1;
    const int w0   = (wid & 1) * 16 + g;
    const int hwc  = h_lo * RS + w0;             // thread-constant offset

    int abase[2 * NKS];
    #pragma unroll
    for (int ks = 0; ks < NKS; ks++) {
        #pragma unroll
        for (int slot = 0; slot < 2; slot++) {
            const int j  = ks * 8 + 4 * slot + t4;
            const int jj = (j < 28) ? j : (j - 28);
            const int dl = (j < 28) ? 0 : 2;
            const int t  = (jj < 27) ? jj : 26;
            const int ex = (jj == 27) ? 1 : 0;
            abase[ks * 2 + slot] = (t / 3) * PS + (t % 3 + ex) * RS + dl + hwc;
        }
    }

    const int ch0 = 2 * t4;
    float bm_m[4]  = { sbm[ch0], sbm[ch0 + 1], sbm[ch0 + 8], sbm[ch0 + 9] };
    float bm_f[4]  = { sbm[COUT + ch0], sbm[COUT + ch0 + 1],
                       sbm[COUT + ch0 + 8], sbm[COUT + ch0 + 9] };

    float s4[4] = {0.f, 0.f, 0.f, 0.f};
    float q4[4] = {0.f, 0.f, 0.f, 0.f};

    uint2* yu = (uint2*)g_yh + (((size_t)(b * DOUT + d)) << 12)
              + (wid * 16 + g) * 4 + t4;

    #pragma unroll
    for (int t = 0; t < 8; t++) {
        float acc0[4] = {0.f, 0.f, 0.f, 0.f};
        float acc1[4] = {0.f, 0.f, 0.f, 0.f};

        #pragma unroll
        for (int ks = 0; ks < NKS; ks++) {
            const int p0 = abase[ks * 2 + 0] + t * (4 * RS);   // imm after unroll
            const int p1 = abase[ks * 2 + 1] + t * (4 * RS);
            const uint32_t a0 = slab[p0];
            const uint32_t a1 = slab[p0 + 8];
            const uint32_t a2 = slab[p1];
            const uint32_t a3 = slab[p1 + 8];

            const uint4 bb = Bpack[ks * 32 + lid];

            mma_f16(acc0, a0, a1, a2, a3, bb.x, bb.y);
            mma_f16(acc1, a0, a1, a2, a3, bb.z, bb.w);
        }

        const float v00 = fmaf(acc0[0], bm_m[0], bm_f[0]);
        const float v01 = fmaf(acc0[1], bm_m[1], bm_f[1]);
        const float v02 = fmaf(acc0[2], bm_m[0], bm_f[0]);
        const float v03 = fmaf(acc0[3], bm_m[1], bm_f[1]);
        const float v10 = fmaf(acc1[0], bm_m[2], bm_f[2]);
        const float v11 = fmaf(acc1[1], bm_m[3], bm_f[3]);
        const float v12 = fmaf(acc1[2], bm_m[2], bm_f[2]);
        const float v13 = fmaf(acc1[3], bm_m[3], bm_f[3]);

        s4[0] += v00 + v02;  q4[0] += v00 * v00 + v02 * v02;
        s4[1] += v01 + v03;  q4[1] += v01 * v01 + v03 * v03;
        s4[2] += v10 + v12;  q4[2] += v10 * v10 + v12 * v12;
        s4[3] += v11 + v13;  q4[3] += v11 * v11 + v13 * v13;

        __half2 ha = __floats2half2_rn(v00, v01);
        __half2 hb = __floats2half2_rn(v10, v11);
        __half2 hc = __floats2half2_rn(v02, v03);
        __half2 hd = __floats2half2_rn(v12, v13);
        uint2 u0, u1;
        u0.x = *reinterpret_cast<uint32_t*>(&ha);
        u0.y = *reinterpret_cast<uint32_t*>(&hb);
        u1.x = *reinterpret_cast<uint32_t*>(&hc);
        u1.y = *reinterpret_cast<uint32_t*>(&hd);
        yu[t * 512]      = u0;                   // imm after unroll
        yu[t * 512 + 32] = u1;
    }

    #pragma unroll
    for (int j = 0; j < 4; j++) {
        #pragma unroll
        for (int off = 16; off >= 4; off >>= 1) {
            s4[j] += __shfl_down_sync(0xffffffffu, s4[j], off);
            q4[j] += __shfl_down_sync(0xffffffffu, q4[j], off);
        }
    }
    if (lid < 4) {
        const int c0 = 2 * lid;
        sred[wid][c0][0]     = s4[0];  sred[wid][c0][1]     = q4[0];
        sred[wid][c0 + 1][0] = s4[1];  sred[wid][c0 + 1][1] = q4[1];
        sred[wid][c0 + 8][0] = s4[2];  sred[wid][c0 + 8][1] = q4[2];
        sred[wid][c0 + 9][0] = s4[3];  sred[wid][c0 + 9][1] = q4[3];
    }
    __syncthreads();
    if (tid < 32) {
        const int c = tid & 15, which = tid >> 4;
        float v = 0.f;
        #pragma unroll
        for (int wi = 0; wi < 8; wi++) v += sred[wi][c][which];
        g_part[((b * COUT + c) * DOUT + d) * 2 + which] = v;
    }
}

// ---------------------------------------------------------------------------
// Kernel 2: fold partials; read interleaved fp16 y (32B/px, coalesced);
// normalize/clamp/mult in f32; max over c; reversed bids for L2 reuse.
// ---------------------------------------------------------------------------
__global__ void __launch_bounds__(256) norm_kernel(
    const float* __restrict__ mult,
    float* __restrict__ out)
{
    const int d   = (DOUT - 1) - blockIdx.x;
    const int b   = (NB - 1) - blockIdx.y;
    const int tid = threadIdx.x;

    __shared__ float sa[COUT], sb2[COUT], smu[COUT];

    if (tid < COUT) {
        float s = 0.0f, q = 0.0f;
        #pragma unroll
        for (int dd = 0; dd < DOUT; dd++) {
            s += g_part[((b * COUT + tid) * DOUT + dd) * 2];
            q += g_part[((b * COUT + tid) * DOUT + dd) * 2 + 1];
        }
        const float invN = 1.0f / (float)(DOUT * HOUT * WOUT);
        const float mean = s * invN;
        const float var  = q * invN - mean * mean;
        const float rs   = rsqrtf(var + 1e-5f);
        sa[tid]  = rs;
        sb2[tid] = -mean * rs;
        smu[tid] = mult[tid];
    }
    __syncthreads();

    float a[16], b2[16], mm[16];
    #pragma unroll
    for (int q = 0; q < 16; q++) {
        const int c = 2 * (q >> 2) + (q & 1) + ((q >> 1) & 1) * 8;
        a[q] = sa[c]; b2[q] = sb2[c]; mm[q] = smu[c];
    }

    const uint4* yh4 = (const uint4*)g_yh + (((size_t)(b * DOUT + d)) << 11);
    float* op = out + (((size_t)b * DOUT + d) << 10);

    #pragma unroll
    for (int it = 0; it < 4; it++) {
        const int r = tid + it * 256;
        const uint4 q0 = yh4[r * 2];
        const uint4 q1 = yh4[r * 2 + 1];
        const uint32_t hw[8] = { q0.x, q0.y, q0.z, q0.w, q1.x, q1.y, q1.z, q1.w };

        float m = -INFINITY;
        #pragma unroll
        for (int p = 0; p < 8; p++) {
            const float2 f2 = __half22float2(*reinterpret_cast<const __half2*>(&hw[p]));
            const int c = 2 * p;
            float v0 = fmaf(f2.x, a[c], b2[c]);
            v0 = fminf(fmaxf(v0, -1.0f), 1.0f) * mm[c];
            float v1 = fmaf(f2.y, a[c + 1], b2[c + 1]);
            v1 = fminf(fmaxf(v1, -1.0f), 1.0f) * mm[c + 1];
            m = fmaxf(m, fmaxf(v0, v1));
        }
        op[r] = m;
    }
}

// ---------------------------------------------------------------------------
extern "C" void kernel_launch(void* const* d_in, const int* in_sizes, int n_in,
                              void* d_out, int out_size)
{
    const float* x    = (const float*)d_in[0];
    const float* cw   = (const float*)d_in[1];
    const float* cb   = (const float*)d_in[2];
    const float* mult = (const float*)d_in[3];
    float* out = (float*)d_out;

    cudaFuncSetAttribute(conv_kernel,
                         cudaFuncAttributeMaxDynamicSharedMemorySize,
                         DSMEM_BYTES);

    dim3 grid(DOUT, NB);
    // 3 dummies: capture slot = our launch #3 => conv_kernel gets profiled.
    dummy_kernel<<<1, 32>>>();
    dummy_kernel<<<1, 32>>>();
    dummy_kernel<<<1, 32>>>();
    conv_kernel<<<grid, 256, DSMEM_BYTES>>>(x, cw, cb, mult);
    norm_kernel<<<grid, 256>>>(mult, out);
}

// round 15
// speedup vs baseline: 1.0751x; 1.0751x over previous
#include <cuda_runtime.h>
#include <cuda_fp16.h>
#include <math.h>
#include <cstdint>

#define NB   128
#define CIN  3
#define DIN  18
#define HIN  34
#define WIN  34
#define HW   (HIN * WIN)
#define COUT 16
#define DOUT 16
#define HOUT 32
#define WOUT 32

#define NKS     7            // 112 k = 56 pairs = 7 k-steps of 16
#define RS      40           // slab row stride (u32),  == 8  mod 32
#define PS      1368         // slab plane stride (u32),== 24 mod 32
#define SLAB32  (9 * PS + 48)     // 12360 u32 slots

// dynamic smem: [ slab fp16x2 u32[SLAB32] | Bpack uint4[7*32] ]
#define DSMEM_BYTES (SLAB32 * 4 + NKS * 32 * 16)

// Scratch (device globals: allocation-free per harness rules)
// y fp16, channel-pair-interleaved channel-last:
//   px block (32B) = [c0c1 | c8c9 | c2c3 | c10c11 | c4c5 | c12c13 | c6c7 | c14c15]
__device__ __half2 g_yh[(size_t)NB * DOUT * 1024 * 8];          // 67 MB
__device__ float   g_part[NB * COUT * DOUT * 2];

__device__ __forceinline__ void mma_f16(float* c,
                                        uint32_t a0, uint32_t a1, uint32_t a2, uint32_t a3,
                                        uint32_t b0, uint32_t b1) {
    asm volatile(
        "mma.sync.aligned.m16n8k16.row.col.f32.f16.f16.f32 "
        "{%0,%1,%2,%3}, {%4,%5,%6,%7}, {%8,%9}, {%0,%1,%2,%3};"
        : "+f"(c[0]), "+f"(c[1]), "+f"(c[2]), "+f"(c[3])
        : "r"(a0), "r"(a1), "r"(a2), "r"(a3), "r"(b0), "r"(b1));
}

// weight for phase-major k': j=k>>1 pair index, i=k&1.
// j<27: tap j, kw i | j==27: pad | j in [28,55): tap j-28, kw2 (i==0) | j==55: pad
__device__ __forceinline__ float wval2(const float* __restrict__ cw, int c, int k) {
    const int j = k >> 1, i = k & 1;
    if (j < 27)              return cw[c * 81 + j * 3 + i];
    if (j >= 28 && j < 55 && i == 0) return cw[c * 81 + (j - 28) * 3 + 2];
    return 0.0f;
}

// ---------------------------------------------------------------------------
// Kernel 1: conv3d + bias + channel-mult, fp16 mma implicit GEMM.
// Phase-major k-mapping => provably conflict-free A LDS ({0,8,16,24} mod 32).
// Grid (DOUT, NB), 256 threads, 4 CTAs/SM.  (R13 structure, verbatim.)
// ---------------------------------------------------------------------------
__global__ void __launch_bounds__(256, 4) conv_kernel(
    const float* __restrict__ x,
    const float* __restrict__ cw,
    const float* __restrict__ cb,
    const float* __restrict__ mult)
{
    extern __shared__ uint32_t slab[];
    uint4* Bpack = (uint4*)(slab + SLAB32);

    __shared__ float sbm[2 * COUT];
    __shared__ float sred[8][COUT][2];

    const int tid = threadIdx.x;
    const int wid = tid >> 5;
    const int lid = tid & 31;
    const int d   = blockIdx.x;
    const int b   = blockIdx.y;

    // ---- build fp16x2 pair slab: slot p = (x[p], x[p+1]) ----
    const float* xb = x + (size_t)b * (CIN * DIN * HW);
    for (int i = tid; i < 9 * 1156; i += 256) {
        const int plane = i / 1156;              // ci*3 + kd
        const int pos   = i - plane * 1156;
        const int h     = pos / 34;
        const int w     = pos - h * 34;
        const int ci    = plane / 3;
        const int kd    = plane - ci * 3;
        const float* src = xb + ci * (DIN * HW) + (d + kd) * HW + pos;
        const float f0 = __ldg(src);
        const float f1 = (w < 33) ? __ldg(src + 1) : 0.0f;
        __half2 h2 = __floats2half2_rn(f0, f1);
        slab[plane * PS + h * RS + w] = *reinterpret_cast<uint32_t*>(&h2);
    }
    // tiny zero-fill: plane-8 row 34 (read by the j=27/55 pad quads at h=31)
    if (tid < 48) slab[8 * PS + 34 * RS + tid] = 0;

    // ---- build packed B-frag table (phase-major map): Bpack[ks*32 + lane] ----
    for (int i = tid; i < NKS * 32; i += 256) {
        const int ks  = i >> 5;
        const int l   = i & 31;
        const int tt4 = l & 3;
        const int gg  = l >> 2;
        const int k0  = ks * 16 + tt4 * 2;
        __half2 p0 = __floats2half2_rn(wval2(cw, gg, k0),     wval2(cw, gg, k0 + 1));
        __half2 p1 = __floats2half2_rn(wval2(cw, gg, k0 + 8), wval2(cw, gg, k0 + 9));
        __half2 p2 = __floats2half2_rn(wval2(cw, gg + 8, k0),     wval2(cw, gg + 8, k0 + 1));
        __half2 p3 = __floats2half2_rn(wval2(cw, gg + 8, k0 + 8), wval2(cw, gg + 8, k0 + 9));
        uint4 v;
        v.x = *reinterpret_cast<uint32_t*>(&p0);
        v.y = *reinterpret_cast<uint32_t*>(&p1);
        v.z = *reinterpret_cast<uint32_t*>(&p2);
        v.w = *reinterpret_cast<uint32_t*>(&p3);
        Bpack[i] = v;
    }
    if (tid < COUT) { sbm[tid] = mult[tid]; sbm[COUT + tid] = cb[tid] * mult[tid]; }
    __syncthreads();

    // ---- per-lane A base slots (phase-major): j = ks*8 + 4*slot + t4 ----
    const int t4 = lid & 3;
    const int g  = lid >> 2;
    int abase[2 * NKS];
    #pragma unroll
    for (int ks = 0; ks < NKS; ks++) {
        #pragma unroll
        for (int slot = 0; slot < 2; slot++) {
            const int j  = ks * 8 + 4 * slot + t4;
            const int jj = (j < 28) ? j : (j - 28);
            const int dl = (j < 28) ? 0 : 2;
            const int t  = (jj < 27) ? jj : 26;
            const int ex = (jj == 27) ? 1 : 0;
            abase[ks * 2 + slot] = (t / 3) * PS + (t % 3 + ex) * RS + dl;
        }
    }

    const int h_lo = wid >> 1;
    const int w0   = (wid & 1) * 16 + g;

    const int ch0 = 2 * t4;
    float bm_m[4]  = { sbm[ch0], sbm[ch0 + 1], sbm[ch0 + 8], sbm[ch0 + 9] };
    float bm_f[4]  = { sbm[COUT + ch0], sbm[COUT + ch0 + 1],
                       sbm[COUT + ch0 + 8], sbm[COUT + ch0 + 9] };

    float s4[4] = {0.f, 0.f, 0.f, 0.f};
    float q4[4] = {0.f, 0.f, 0.f, 0.f};

    // y uint2 view: 4 uint2 per px block; thread owns sub-block t4 of its px
    uint2* yu = (uint2*)g_yh + (((size_t)(b * DOUT + d)) << 12)
              + (wid * 16 + g) * 4 + t4;

    for (int t = 0; t < 8; t++) {
        float acc0[4] = {0.f, 0.f, 0.f, 0.f};
        float acc1[4] = {0.f, 0.f, 0.f, 0.f};

        const int hw0 = (t * 4 + h_lo) * RS + w0;

        #pragma unroll
        for (int ks = 0; ks < NKS; ks++) {
            const int p0 = abase[ks * 2 + 0] + hw0;
            const int p1 = abase[ks * 2 + 1] + hw0;
            const uint32_t a0 = slab[p0];
            const uint32_t a1 = slab[p0 + 8];
            const uint32_t a2 = slab[p1];
            const uint32_t a3 = slab[p1 + 8];

            const uint4 bb = Bpack[ks * 32 + lid];

            mma_f16(acc0, a0, a1, a2, a3, bb.x, bb.y);
            mma_f16(acc1, a0, a1, a2, a3, bb.z, bb.w);
        }

        // epilogue: fused bias*mult via FMA, stats (f32), uint2 stores
        const float v00 = fmaf(acc0[0], bm_m[0], bm_f[0]);
        const float v01 = fmaf(acc0[1], bm_m[1], bm_f[1]);
        const float v02 = fmaf(acc0[2], bm_m[0], bm_f[0]);
        const float v03 = fmaf(acc0[3], bm_m[1], bm_f[1]);
        const float v10 = fmaf(acc1[0], bm_m[2], bm_f[2]);
        const float v11 = fmaf(acc1[1], bm_m[3], bm_f[3]);
        const float v12 = fmaf(acc1[2], bm_m[2], bm_f[2]);
        const float v13 = fmaf(acc1[3], bm_m[3], bm_f[3]);

        s4[0] += v00 + v02;  q4[0] += v00 * v00 + v02 * v02;
        s4[1] += v01 + v03;  q4[1] += v01 * v01 + v03 * v03;
        s4[2] += v10 + v12;  q4[2] += v10 * v10 + v12 * v12;
        s4[3] += v11 + v13;  q4[3] += v11 * v11 + v13 * v13;

        __half2 ha = __floats2half2_rn(v00, v01);
        __half2 hb = __floats2half2_rn(v10, v11);
        __half2 hc = __floats2half2_rn(v02, v03);
        __half2 hd = __floats2half2_rn(v12, v13);
        uint2 u0, u1;
        u0.x = *reinterpret_cast<uint32_t*>(&ha);
        u0.y = *reinterpret_cast<uint32_t*>(&hb);
        u1.x = *reinterpret_cast<uint32_t*>(&hc);
        u1.y = *reinterpret_cast<uint32_t*>(&hd);
        yu[t * 512]      = u0;                   // px = t*128 + wid*16 + g
        yu[t * 512 + 32] = u1;                   // px + 8
    }

    #pragma unroll
    for (int j = 0; j < 4; j++) {
        #pragma unroll
        for (int off = 16; off >= 4; off >>= 1) {
            s4[j] += __shfl_down_sync(0xffffffffu, s4[j], off);
            q4[j] += __shfl_down_sync(0xffffffffu, q4[j], off);
        }
    }
    if (lid < 4) {
        const int c0 = 2 * lid;
        sred[wid][c0][0]     = s4[0];  sred[wid][c0][1]     = q4[0];
        sred[wid][c0 + 1][0] = s4[1];  sred[wid][c0 + 1][1] = q4[1];
        sred[wid][c0 + 8][0] = s4[2];  sred[wid][c0 + 8][1] = q4[2];
        sred[wid][c0 + 9][0] = s4[3];  sred[wid][c0 + 9][1] = q4[3];
    }
    __syncthreads();
    if (tid < 32) {
        const int c = tid & 15, which = tid >> 4;
        float v = 0.f;
        #pragma unroll
        for (int wi = 0; wi < 8; wi++) v += sred[wi][c][which];
        g_part[((b * COUT + c) * DOUT + d) * 2 + which] = v;
    }
}

// ---------------------------------------------------------------------------
// Kernel 2: fold partials; read interleaved fp16 y (32B/px, coalesced);
// normalize/clamp/mult in f32; max over c; reversed bids for L2 reuse.
// ---------------------------------------------------------------------------
__global__ void __launch_bounds__(256) norm_kernel(
    const float* __restrict__ mult,
    float* __restrict__ out)
{
    const int d   = (DOUT - 1) - blockIdx.x;
    const int b   = (NB - 1) - blockIdx.y;
    const int tid = threadIdx.x;

    __shared__ float sa[COUT], sb2[COUT], smu[COUT];

    if (tid < COUT) {
        float s = 0.0f, q = 0.0f;
        #pragma unroll
        for (int dd = 0; dd < DOUT; dd++) {
            s += g_part[((b * COUT + tid) * DOUT + dd) * 2];
            q += g_part[((b * COUT + tid) * DOUT + dd) * 2 + 1];
        }
        const float invN = 1.0f / (float)(DOUT * HOUT * WOUT);
        const float mean = s * invN;
        const float var  = q * invN - mean * mean;
        const float rs   = rsqrtf(var + 1e-5f);
        sa[tid]  = rs;
        sb2[tid] = -mean * rs;
        smu[tid] = mult[tid];
    }
    __syncthreads();

    // tables in half-position order: position q -> channel 2*(q>>2)+(q&1)+((q>>1)&1)*8
    float a[16], b2[16], mm[16];
    #pragma unroll
    for (int q = 0; q < 16; q++) {
        const int c = 2 * (q >> 2) + (q & 1) + ((q >> 1) & 1) * 8;
        a[q] = sa[c]; b2[q] = sb2[c]; mm[q] = smu[c];
    }

    const uint4* yh4 = (const uint4*)g_yh + (((size_t)(b * DOUT + d)) << 11);
    float* op = out + (((size_t)b * DOUT + d) << 10);

    #pragma unroll
    for (int it = 0; it < 4; it++) {
        const int r = tid + it * 256;
        const uint4 q0 = yh4[r * 2];
        const uint4 q1 = yh4[r * 2 + 1];
        const uint32_t hw[8] = { q0.x, q0.y, q0.z, q0.w, q1.x, q1.y, q1.z, q1.w };

        float m = -INFINITY;
        #pragma unroll
        for (int p = 0; p < 8; p++) {
            const float2 f2 = __half22float2(*reinterpret_cast<const __half2*>(&hw[p]));
            const int c = 2 * p;
            float v0 = fmaf(f2.x, a[c], b2[c]);
            v0 = fminf(fmaxf(v0, -1.0f), 1.0f) * mm[c];
            float v1 = fmaf(f2.y, a[c + 1], b2[c + 1]);
            v1 = fminf(fmaxf(v1, -1.0f), 1.0f) * mm[c + 1];
            m = fmaxf(m, fmaxf(v0, v1));
        }
        op[r] = m;
    }
}

// ---------------------------------------------------------------------------
extern "C" void kernel_launch(void* const* d_in, const int* in_sizes, int n_in,
                              void* d_out, int out_size)
{
    const float* x    = (const float*)d_in[0];
    const float* cw   = (const float*)d_in[1];
    const float* cb   = (const float*)d_in[2];
    const float* mult = (const float*)d_in[3];
    float* out = (float*)d_out;

    cudaFuncSetAttribute(conv_kernel,
                         cudaFuncAttributeMaxDynamicSharedMemorySize,
                         DSMEM_BYTES);

    dim3 grid(DOUT, NB);
    // No dummy kernels: profiling phase done, stop paying ~5us of node overhead.
    conv_kernel<<<grid, 256, DSMEM_BYTES>>>(x, cw, cb, mult);
    norm_kernel<<<grid, 256>>>(mult, out);
}

// round 16
// speedup vs baseline: 1.0946x; 1.0181x over previous
#include <cuda_runtime.h>
#include <cuda_fp16.h>
#include <math.h>
#include <cstdint>

#define NB   128
#define CIN  3
#define DIN  18
#define HIN  34
#define WIN  34
#define HW   (HIN * WIN)
#define COUT 16
#define DOUT 16
#define HOUT 32
#define WOUT 32

#define NKS     7            // 112 k = 56 pairs = 7 k-steps of 16
#define RS      40           // slab row stride (u32),  == 8  mod 32
#define PS      1368         // slab plane stride (u32),== 24 mod 32
#define SLAB32  (9 * PS + 48)     // 12360 u32 slots

// dynamic smem: [ slab fp16x2 u32[SLAB32] | Bpack uint4[7*32] ]
#define DSMEM_BYTES (SLAB32 * 4 + NKS * 32 * 16)

// Scratch (device globals: allocation-free per harness rules)
// y fp16, channel-pair-interleaved channel-last:
//   px block (32B) = [c0c1 | c8c9 | c2c3 | c10c11 | c4c5 | c12c13 | c6c7 | c14c15]
__device__ __half2 g_yh[(size_t)NB * DOUT * 1024 * 8];          // 67 MB
__device__ float   g_part[NB * COUT * DOUT * 2];

__device__ __forceinline__ void mma_f16(float* c,
                                        uint32_t a0, uint32_t a1, uint32_t a2, uint32_t a3,
                                        uint32_t b0, uint32_t b1) {
    asm volatile(
        "mma.sync.aligned.m16n8k16.row.col.f32.f16.f16.f32 "
        "{%0,%1,%2,%3}, {%4,%5,%6,%7}, {%8,%9}, {%0,%1,%2,%3};"
        : "+f"(c[0]), "+f"(c[1]), "+f"(c[2]), "+f"(c[3])
        : "r"(a0), "r"(a1), "r"(a2), "r"(a3), "r"(b0), "r"(b1));
}

// weight for phase-major k': j=k>>1 pair index, i=k&1.
// j<27: tap j, kw i | j==27: pad | j in [28,55): tap j-28, kw2 (i==0) | j==55: pad
__device__ __forceinline__ float wval2(const float* __restrict__ cw, int c, int k) {
    const int j = k >> 1, i = k & 1;
    if (j < 27)              return cw[c * 81 + j * 3 + i];
    if (j >= 28 && j < 55 && i == 0) return cw[c * 81 + (j - 28) * 3 + 2];
    return 0.0f;
}

// ---------------------------------------------------------------------------
// Kernel 1: conv3d + bias + channel-mult, fp16 mma implicit GEMM.
// Phase-major k-mapping => provably conflict-free A LDS ({0,8,16,24} mod 32).
// Grid (DOUT, NB), 256 threads, 4 CTAs/SM.  (R13 structure, verbatim.)
// ---------------------------------------------------------------------------
__global__ void __launch_bounds__(256, 4) conv_kernel(
    const float* __restrict__ x,
    const float* __restrict__ cw,
    const float* __restrict__ cb,
    const float* __restrict__ mult)
{
    extern __shared__ uint32_t slab[];
    uint4* Bpack = (uint4*)(slab + SLAB32);

    __shared__ float sbm[2 * COUT];
    __shared__ float sred[8][COUT][2];

    const int tid = threadIdx.x;
    const int wid = tid >> 5;
    const int lid = tid & 31;
    const int d   = blockIdx.x;
    const int b   = blockIdx.y;

    // ---- build fp16x2 pair slab: slot p = (x[p], x[p+1]) ----
    const float* xb = x + (size_t)b * (CIN * DIN * HW);
    for (int i = tid; i < 9 * 1156; i += 256) {
        const int plane = i / 1156;              // ci*3 + kd
        const int pos   = i - plane * 1156;
        const int h     = pos / 34;
        const int w     = pos - h * 34;
        const int ci    = plane / 3;
        const int kd    = plane - ci * 3;
        const float* src = xb + ci * (DIN * HW) + (d + kd) * HW + pos;
        const float f0 = __ldg(src);
        const float f1 = (w < 33) ? __ldg(src + 1) : 0.0f;
        __half2 h2 = __floats2half2_rn(f0, f1);
        slab[plane * PS + h * RS + w] = *reinterpret_cast<uint32_t*>(&h2);
    }
    // tiny zero-fill: plane-8 row 34 (read by the j=27/55 pad quads at h=31)
    if (tid < 48) slab[8 * PS + 34 * RS + tid] = 0;

    // ---- build packed B-frag table (phase-major map): Bpack[ks*32 + lane] ----
    for (int i = tid; i < NKS * 32; i += 256) {
        const int ks  = i >> 5;
        const int l   = i & 31;
        const int tt4 = l & 3;
        const int gg  = l >> 2;
        const int k0  = ks * 16 + tt4 * 2;
        __half2 p0 = __floats2half2_rn(wval2(cw, gg, k0),     wval2(cw, gg, k0 + 1));
        __half2 p1 = __floats2half2_rn(wval2(cw, gg, k0 + 8), wval2(cw, gg, k0 + 9));
        __half2 p2 = __floats2half2_rn(wval2(cw, gg + 8, k0),     wval2(cw, gg + 8, k0 + 1));
        __half2 p3 = __floats2half2_rn(wval2(cw, gg + 8, k0 + 8), wval2(cw, gg + 8, k0 + 9));
        uint4 v;
        v.x = *reinterpret_cast<uint32_t*>(&p0);
        v.y = *reinterpret_cast<uint32_t*>(&p1);
        v.z = *reinterpret_cast<uint32_t*>(&p2);
        v.w = *reinterpret_cast<uint32_t*>(&p3);
        Bpack[i] = v;
    }
    if (tid < COUT) { sbm[tid] = mult[tid]; sbm[COUT + tid] = cb[tid] * mult[tid]; }
    __syncthreads();

    // ---- per-lane A base slots (phase-major): j = ks*8 + 4*slot + t4 ----
    const int t4 = lid & 3;
    const int g  = lid >> 2;
    int abase[2 * NKS];
    #pragma unroll
    for (int ks = 0; ks < NKS; ks++) {
        #pragma unroll
        for (int slot = 0; slot < 2; slot++) {
            const int j  = ks * 8 + 4 * slot + t4;
            const int jj = (j < 28) ? j : (j - 28);
            const int dl = (j < 28) ? 0 : 2;
            const int t  = (jj < 27) ? jj : 26;
            const int ex = (jj == 27) ? 1 : 0;
            abase[ks * 2 + slot] = (t / 3) * PS + (t % 3 + ex) * RS + dl;
        }
    }

    const int h_lo = wid >> 1;
    const int w0   = (wid & 1) * 16 + g;

    const int ch0 = 2 * t4;
    float bm_m[4]  = { sbm[ch0], sbm[ch0 + 1], sbm[ch0 + 8], sbm[ch0 + 9] };
    float bm_f[4]  = { sbm[COUT + ch0], sbm[COUT + ch0 + 1],
                       sbm[COUT + ch0 + 8], sbm[COUT + ch0 + 9] };

    float s4[4] = {0.f, 0.f, 0.f, 0.f};
    float q4[4] = {0.f, 0.f, 0.f, 0.f};

    // y uint2 view: 4 uint2 per px block; thread owns sub-block t4 of its px
    uint2* yu = (uint2*)g_yh + (((size_t)(b * DOUT + d)) << 12)
              + (wid * 16 + g) * 4 + t4;

    for (int t = 0; t < 8; t++) {
        float acc0[4] = {0.f, 0.f, 0.f, 0.f};
        float acc1[4] = {0.f, 0.f, 0.f, 0.f};

        const int hw0 = (t * 4 + h_lo) * RS + w0;

        #pragma unroll
        for (int ks = 0; ks < NKS; ks++) {
            const int p0 = abase[ks * 2 + 0] + hw0;
            const int p1 = abase[ks * 2 + 1] + hw0;
            const uint32_t a0 = slab[p0];
            const uint32_t a1 = slab[p0 + 8];
            const uint32_t a2 = slab[p1];
            const uint32_t a3 = slab[p1 + 8];

            const uint4 bb = Bpack[ks * 32 + lid];

            mma_f16(acc0, a0, a1, a2, a3, bb.x, bb.y);
            mma_f16(acc1, a0, a1, a2, a3, bb.z, bb.w);
        }

        // epilogue: fused bias*mult via FMA, stats (f32), uint2 stores
        const float v00 = fmaf(acc0[0], bm_m[0], bm_f[0]);
        const float v01 = fmaf(acc0[1], bm_m[1], bm_f[1]);
        const float v02 = fmaf(acc0[2], bm_m[0], bm_f[0]);
        const float v03 = fmaf(acc0[3], bm_m[1], bm_f[1]);
        const float v10 = fmaf(acc1[0], bm_m[2], bm_f[2]);
        const float v11 = fmaf(acc1[1], bm_m[3], bm_f[3]);
        const float v12 = fmaf(acc1[2], bm_m[2], bm_f[2]);
        const float v13 = fmaf(acc1[3], bm_m[3], bm_f[3]);

        s4[0] += v00 + v02;  q4[0] += v00 * v00 + v02 * v02;
        s4[1] += v01 + v03;  q4[1] += v01 * v01 + v03 * v03;
        s4[2] += v10 + v12;  q4[2] += v10 * v10 + v12 * v12;
        s4[3] += v11 + v13;  q4[3] += v11 * v11 + v13 * v13;

        __half2 ha = __floats2half2_rn(v00, v01);
        __half2 hb = __floats2half2_rn(v10, v11);
        __half2 hc = __floats2half2_rn(v02, v03);
        __half2 hd = __floats2half2_rn(v12, v13);
        uint2 u0, u1;
        u0.x = *reinterpret_cast<uint32_t*>(&ha);
        u0.y = *reinterpret_cast<uint32_t*>(&hb);
        u1.x = *reinterpret_cast<uint32_t*>(&hc);
        u1.y = *reinterpret_cast<uint32_t*>(&hd);
        yu[t * 512]      = u0;                   // px = t*128 + wid*16 + g
        yu[t * 512 + 32] = u1;                   // px + 8
    }

    #pragma unroll
    for (int j = 0; j < 4; j++) {
        #pragma unroll
        for (int off = 16; off >= 4; off >>= 1) {
            s4[j] += __shfl_down_sync(0xffffffffu, s4[j], off);
            q4[j] += __shfl_down_sync(0xffffffffu, q4[j], off);
        }
    }
    if (lid < 4) {
        const int c0 = 2 * lid;
        sred[wid][c0][0]     = s4[0];  sred[wid][c0][1]     = q4[0];
        sred[wid][c0 + 1][0] = s4[1];  sred[wid][c0 + 1][1] = q4[1];
        sred[wid][c0 + 8][0] = s4[2];  sred[wid][c0 + 8][1] = q4[2];
        sred[wid][c0 + 9][0] = s4[3];  sred[wid][c0 + 9][1] = q4[3];
    }
    __syncthreads();
    if (tid < 32) {
        const int c = tid & 15, which = tid >> 4;
        float v = 0.f;
        #pragma unroll
        for (int wi = 0; wi < 8; wi++) v += sred[wi][c][which];
        g_part[((b * COUT + c) * DOUT + d) * 2 + which] = v;
    }
}

// ---------------------------------------------------------------------------
// Kernel 2: fold partials; FRONT-LOADED 8x LDG.128 per thread (MLP 8) and
// channel tables in smem (broadcast LDS) to keep regs low / occupancy up.
// Reversed bids for L2 reuse.
// ---------------------------------------------------------------------------
__global__ void __launch_bounds__(256) norm_kernel(
    const float* __restrict__ mult,
    float* __restrict__ out)
{
    const int d   = (DOUT - 1) - blockIdx.x;
    const int b   = (NB - 1) - blockIdx.y;
    const int tid = threadIdx.x;

    __shared__ float sa[COUT], sb2[COUT], smu[COUT];

    if (tid < COUT) {
        float s = 0.0f, q = 0.0f;
        #pragma unroll
        for (int dd = 0; dd < DOUT; dd++) {
            s += g_part[((b * COUT + tid) * DOUT + dd) * 2];
            q += g_part[((b * COUT + tid) * DOUT + dd) * 2 + 1];
        }
        const float invN = 1.0f / (float)(DOUT * HOUT * WOUT);
        const float mean = s * invN;
        const float var  = q * invN - mean * mean;
        const float rs   = rsqrtf(var + 1e-5f);
        sa[tid]  = rs;
        sb2[tid] = -mean * rs;
        smu[tid] = mult[tid];
    }
    __syncthreads();

    const uint4* yh4 = (const uint4*)g_yh + (((size_t)(b * DOUT + d)) << 11);
    float* op = out + (((size_t)b * DOUT + d) << 10);

    // front-load ALL 8 LDG.128 (independent) for maximum MLP
    uint4 q[8];
    #pragma unroll
    for (int it = 0; it < 4; it++) {
        const int r = tid + it * 256;
        q[2 * it]     = yh4[r * 2];
        q[2 * it + 1] = yh4[r * 2 + 1];
    }

    #pragma unroll
    for (int it = 0; it < 4; it++) {
        const int r = tid + it * 256;
        const uint32_t hw[8] = { q[2*it].x, q[2*it].y, q[2*it].z, q[2*it].w,
                                 q[2*it+1].x, q[2*it+1].y, q[2*it+1].z, q[2*it+1].w };
        float m = -INFINITY;
        #pragma unroll
        for (int p = 0; p < 8; p++) {
            // position 2p   -> channel c0 = 2*(p>>1) + ((p&1)<<3)   (pairs (c,c+1))
            const int c0 = 2 * (p >> 1) + ((p & 1) << 3);
            const float2 f2 = __half22float2(*reinterpret_cast<const __half2*>(&hw[p]));
            float v0 = fmaf(f2.x, sa[c0], sb2[c0]);
            v0 = fminf(fmaxf(v0, -1.0f), 1.0f) * smu[c0];
            float v1 = fmaf(f2.y, sa[c0 + 1], sb2[c0 + 1]);
            v1 = fminf(fmaxf(v1, -1.0f), 1.0f) * smu[c0 + 1];
            m = fmaxf(m, fmaxf(v0, v1));
        }
        op[r] = m;
    }
}

// ---------------------------------------------------------------------------
extern "C" void kernel_launch(void* const* d_in, const int* in_sizes, int n_in,
                              void* d_out, int out_size)
{
    const float* x    = (const float*)d_in[0];
    const float* cw   = (const float*)d_in[1];
    const float* cb   = (const float*)d_in[2];
    const float* mult = (const float*)d_in[3];
    float* out = (float*)d_out;

    cudaFuncSetAttribute(conv_kernel,
                         cudaFuncAttributeMaxDynamicSharedMemorySize,
                         DSMEM_BYTES);

    dim3 grid(DOUT, NB);
    conv_kernel<<<grid, 256, DSMEM_BYTES>>>(x, cw, cb, mult);
    norm_kernel<<<grid, 256>>>(mult, out);
}